// round 2
// baseline (speedup 1.0000x reference)
#include <cuda_runtime.h>
#include <cuda_bf16.h>
#include <cstdint>

// Problem constants (fixed shapes for this problem)
#define NTOT 100000
#define ETOT 1600000
#define GTOT 1024
#define NB   782          // ceil(NTOT/128) GIN blocks
#define NSCAN 98          // ceil(NTOT/1024)
#define BN_EPS 1e-5f

// ---------------- device scratch (no runtime allocation allowed) ----------------
__device__ float g_bufA[NTOT * 64];       // ping
__device__ float g_bufB[NTOT * 64];       // pong
__device__ int   g_deg[NTOT];
__device__ int   g_rowptr[NTOT + 1];
__device__ int   g_cursor[NTOT];
__device__ int   g_csr[ETOT];
__device__ int   g_bsum[NSCAN];
__device__ int   g_boff[NSCAN];
__device__ float g_stats[NB * 128];       // per-block [sum(64), sumsq(64)]
__device__ float g_scale[5 * 64];         // BN folded: scale = rstd*gamma
__device__ float g_shift[5 * 64];         // shift = beta - mean*scale
__device__ float g_pooled[GTOT * 320];    // raw (pre-BN) per-graph sums
__device__ int   g_cnt[GTOT];             // nodes per graph

// ---------------- zero scratch ----------------
__global__ void zero_kernel() {
    int i0 = blockIdx.x * blockDim.x + threadIdx.x;
    int str = gridDim.x * blockDim.x;
    for (int i = i0; i < GTOT * 320; i += str) g_pooled[i] = 0.f;
    for (int i = i0; i < NTOT; i += str) g_deg[i] = 0;
    for (int i = i0; i < GTOT; i += str) g_cnt[i] = 0;
}

// ---------------- degree histogram + graph-size histogram ----------------
__global__ void hist_kernel(const int* __restrict__ dst, const int* __restrict__ batch) {
    int i = blockIdx.x * blockDim.x + threadIdx.x;
    if (i < ETOT) atomicAdd(&g_deg[dst[i]], 1);
    if (i < NTOT) atomicAdd(&g_cnt[batch[i]], 1);
}

// ---------------- 3-kernel coalesced exclusive scan of degrees ----------------
__global__ void scanA_kernel() {
    __shared__ int s[1024];
    int t = threadIdx.x;
    int i = blockIdx.x * 1024 + t;
    s[t] = (i < NTOT) ? g_deg[i] : 0;
    __syncthreads();
    for (int off = 512; off; off >>= 1) {
        if (t < off) s[t] += s[t + off];
        __syncthreads();
    }
    if (t == 0) g_bsum[blockIdx.x] = s[0];
}

// parallel warp-scan over the 98 block sums (replaces 8.6us serial kernel)
__global__ void scanB_kernel() {
    int t = threadIdx.x;                       // 128 threads
    int v = (t < NSCAN) ? g_bsum[t] : 0;
    int x = v;
#pragma unroll
    for (int off = 1; off < 32; off <<= 1) {
        int y = __shfl_up_sync(0xffffffffu, x, off);
        if ((t & 31) >= off) x += y;
    }
    __shared__ int ws[4];
    if ((t & 31) == 31) ws[t >> 5] = x;
    __syncthreads();
    int add = 0;
#pragma unroll
    for (int w = 0; w < 4; w++) if (w < (t >> 5)) add += ws[w];
    int incl = x + add;
    if (t < NSCAN) g_boff[t] = incl - v;
    if (t == NSCAN - 1) g_rowptr[NTOT] = incl;
}

__global__ void scanC_kernel() {
    __shared__ int s[1024];
    int t = threadIdx.x;
    int i = blockIdx.x * 1024 + t;
    int v = (i < NTOT) ? g_deg[i] : 0;
    s[t] = v;
    __syncthreads();
    for (int off = 1; off < 1024; off <<= 1) {
        int tmp = (t >= off) ? s[t - off] : 0;
        __syncthreads();
        s[t] += tmp;
        __syncthreads();
    }
    int excl = s[t] - v + g_boff[blockIdx.x];
    if (i < NTOT) { g_rowptr[i] = excl; g_cursor[i] = excl; }
}

// ---------------- edge scatter into CSR ----------------
__global__ void scatter_kernel(const int* __restrict__ src, const int* __restrict__ dst) {
    int i = blockIdx.x * blockDim.x + threadIdx.x;
    if (i < ETOT) {
        int d = dst[i];
        int p = atomicAdd(&g_cursor[d], 1);
        g_csr[p] = src[i];
    }
}

// ---------------- q = x @ W1a (11 -> 64), no bias (bias folded into layer0) ----------------
__global__ void gemm_in_kernel(const float* __restrict__ x, const float* __restrict__ W1a) {
    __shared__ float sW[11 * 64];
    __shared__ float sx[4][12];
    int t = threadIdx.x;            // 256
    int nl = t >> 6, c = t & 63;
    int node = blockIdx.x * 4 + nl;
    for (int i = t; i < 11 * 64; i += 256) sW[i] = W1a[i];
    if (t < 44) {
        int n2 = t / 11, k = t % 11;
        int nn = blockIdx.x * 4 + n2;
        sx[n2][k] = (nn < NTOT) ? x[nn * 11 + k] : 0.f;
    }
    __syncthreads();
    if (node < NTOT) {
        float a = 0.f;
#pragma unroll
        for (int k = 0; k < 11; k++) a = fmaf(sx[nl][k], sW[k * 64 + c], a);
        g_bufA[node * 64 + c] = a;
    }
}

// ---------------- fused GIN layer ----------------
// 512 threads per block, 128 nodes. Weights streamed from L1/L2 (not smem) so
// smem ~= 35KB -> 4 blocks/SM = 64 warps/SM for gather latency hiding.
//  (1) CSR gather-sum aggregation (prev-layer BN applied analytically) -> sT
//  (2) GEMM1 (64x64) + ReLU  (skipped for FIRST)
//  (3) GEMM2 (64x64) + bias + ReLU
//  (4) epilogue: store raw h, per-channel sum/sumsq partials, pooled run-length atomics
template <bool FIRST>
__launch_bounds__(512, 4)
__global__ void gin_kernel(const float* __restrict__ Wa, const float* __restrict__ ba,
                           const float* __restrict__ Wb, const float* __restrict__ bb,
                           const int* __restrict__ batch, int layer) {
    const float* hin  = (layer & 1) ? g_bufB : g_bufA;
    float*       hout = (layer & 1) ? g_bufA : g_bufB;
    const float* scale_prev = g_scale + (layer - 1) * 64;
    const float* shift_prev = g_shift + (layer - 1) * 64;

    __shared__ float sT[128 * 66];
    __shared__ float sBa[64];
    __shared__ float sBb[64];
    __shared__ int   sBatch[128];

    int t = threadIdx.x;                    // 512
    int base = blockIdx.x * 128;
    int warp = t >> 5, lane = t & 31;

    if (t < 64) {
        sBb[t] = bb[t];
        if (!FIRST) sBa[t] = ba[t];
    }
    if (t < 128) {
        int n = base + t;
        sBatch[t] = (n < NTOT) ? batch[n] : -1;
    }

    // ---- phase 1: aggregation (16 warps x 8 nodes) ----
    {
        float b0 = 0.f, b1 = 0.f;           // FIRST: bias; else BN scale/shift
        float sc0 = 0.f, sc1 = 0.f, sh0 = 0.f, sh1 = 0.f;
        if (FIRST) {
            b0 = __ldg(&ba[2 * lane]); b1 = __ldg(&ba[2 * lane + 1]);
        } else {
            float2 sc = *(const float2*)(scale_prev + 2 * lane);
            float2 sh = *(const float2*)(shift_prev + 2 * lane);
            sc0 = sc.x; sc1 = sc.y; sh0 = sh.x; sh1 = sh.y;
        }
#pragma unroll 1
        for (int j = 0; j < 8; j++) {
            int r = warp * 8 + j;
            int node = base + r;
            float ax = 0.f, ay = 0.f;
            if (node < NTOT) {
                float2 own = *(const float2*)(hin + (size_t)node * 64 + 2 * lane);
                ax = own.x; ay = own.y;
                int s0 = g_rowptr[node], s1 = g_rowptr[node + 1];
                int e = s0;
                // 4-wide unrolled independent gather (no shfl dependency)
                for (; e + 4 <= s1; e += 4) {
                    int i0 = __ldg(g_csr + e);
                    int i1 = __ldg(g_csr + e + 1);
                    int i2 = __ldg(g_csr + e + 2);
                    int i3 = __ldg(g_csr + e + 3);
                    float2 v0 = *(const float2*)(hin + (size_t)i0 * 64 + 2 * lane);
                    float2 v1 = *(const float2*)(hin + (size_t)i1 * 64 + 2 * lane);
                    float2 v2 = *(const float2*)(hin + (size_t)i2 * 64 + 2 * lane);
                    float2 v3 = *(const float2*)(hin + (size_t)i3 * 64 + 2 * lane);
                    ax += (v0.x + v1.x) + (v2.x + v3.x);
                    ay += (v0.y + v1.y) + (v2.y + v3.y);
                }
                for (; e < s1; e++) {
                    int s = __ldg(g_csr + e);
                    float2 v = *(const float2*)(hin + (size_t)s * 64 + 2 * lane);
                    ax += v.x; ay += v.y;
                }
                if (FIRST) {
                    ax = fmaxf(ax + b0, 0.f);
                    ay = fmaxf(ay + b1, 0.f);
                } else {
                    float kk = (float)(s1 - s0 + 1);
                    ax = fmaf(sc0, ax, kk * sh0);
                    ay = fmaf(sc1, ay, kk * sh1);
                }
            }
            sT[r * 66 + 2 * lane]     = ax;
            sT[r * 66 + 2 * lane + 1] = ay;
        }
    }
    __syncthreads();

    int ty = t >> 4, tx = t & 15;           // 32x16 thread grid; micro-tile 4 rows x 4 cols
    float acc[4][4];

    // ---- phase 2: GEMM1 + ReLU (weights streamed from global, prefetched) ----
    if (!FIRST) {
#pragma unroll
        for (int i = 0; i < 4; i++)
#pragma unroll
            for (int j = 0; j < 4; j++) acc[i][j] = 0.f;
        float4 bn = __ldg((const float4*)(Wa + tx * 4));
#pragma unroll 8
        for (int k = 0; k < 64; k++) {
            float4 b = bn;
            if (k < 63) bn = __ldg((const float4*)(Wa + (k + 1) * 64 + tx * 4));
            float a0 = sT[(ty * 4 + 0) * 66 + k];
            float a1 = sT[(ty * 4 + 1) * 66 + k];
            float a2 = sT[(ty * 4 + 2) * 66 + k];
            float a3 = sT[(ty * 4 + 3) * 66 + k];
            acc[0][0] = fmaf(a0, b.x, acc[0][0]); acc[0][1] = fmaf(a0, b.y, acc[0][1]);
            acc[0][2] = fmaf(a0, b.z, acc[0][2]); acc[0][3] = fmaf(a0, b.w, acc[0][3]);
            acc[1][0] = fmaf(a1, b.x, acc[1][0]); acc[1][1] = fmaf(a1, b.y, acc[1][1]);
            acc[1][2] = fmaf(a1, b.z, acc[1][2]); acc[1][3] = fmaf(a1, b.w, acc[1][3]);
            acc[2][0] = fmaf(a2, b.x, acc[2][0]); acc[2][1] = fmaf(a2, b.y, acc[2][1]);
            acc[2][2] = fmaf(a2, b.z, acc[2][2]); acc[2][3] = fmaf(a2, b.w, acc[2][3]);
            acc[3][0] = fmaf(a3, b.x, acc[3][0]); acc[3][1] = fmaf(a3, b.y, acc[3][1]);
            acc[3][2] = fmaf(a3, b.z, acc[3][2]); acc[3][3] = fmaf(a3, b.w, acc[3][3]);
        }
        __syncthreads();
#pragma unroll
        for (int i = 0; i < 4; i++)
#pragma unroll
            for (int j = 0; j < 4; j++)
                sT[(ty * 4 + i) * 66 + tx * 4 + j] = fmaxf(acc[i][j] + sBa[tx * 4 + j], 0.f);
        __syncthreads();
    }

    // ---- phase 3: GEMM2 ----
#pragma unroll
    for (int i = 0; i < 4; i++)
#pragma unroll
        for (int j = 0; j < 4; j++) acc[i][j] = 0.f;
    {
        float4 bn = __ldg((const float4*)(Wb + tx * 4));
#pragma unroll 8
        for (int k = 0; k < 64; k++) {
            float4 b = bn;
            if (k < 63) bn = __ldg((const float4*)(Wb + (k + 1) * 64 + tx * 4));
            float a0 = sT[(ty * 4 + 0) * 66 + k];
            float a1 = sT[(ty * 4 + 1) * 66 + k];
            float a2 = sT[(ty * 4 + 2) * 66 + k];
            float a3 = sT[(ty * 4 + 3) * 66 + k];
            acc[0][0] = fmaf(a0, b.x, acc[0][0]); acc[0][1] = fmaf(a0, b.y, acc[0][1]);
            acc[0][2] = fmaf(a0, b.z, acc[0][2]); acc[0][3] = fmaf(a0, b.w, acc[0][3]);
            acc[1][0] = fmaf(a1, b.x, acc[1][0]); acc[1][1] = fmaf(a1, b.y, acc[1][1]);
            acc[1][2] = fmaf(a1, b.z, acc[1][2]); acc[1][3] = fmaf(a1, b.w, acc[1][3]);
            acc[2][0] = fmaf(a2, b.x, acc[2][0]); acc[2][1] = fmaf(a2, b.y, acc[2][1]);
            acc[2][2] = fmaf(a2, b.z, acc[2][2]); acc[2][3] = fmaf(a2, b.w, acc[2][3]);
            acc[3][0] = fmaf(a3, b.x, acc[3][0]); acc[3][1] = fmaf(a3, b.y, acc[3][1]);
            acc[3][2] = fmaf(a3, b.z, acc[3][2]); acc[3][3] = fmaf(a3, b.w, acc[3][3]);
        }
    }

    // ---- phase 4: epilogue ----
    float ssum[4] = {0.f, 0.f, 0.f, 0.f};
    float sqr[4]  = {0.f, 0.f, 0.f, 0.f};
    float run[4]  = {0.f, 0.f, 0.f, 0.f};
    int curg = -1;
#pragma unroll
    for (int i = 0; i < 4; i++) {
        int r = ty * 4 + i;
        int node = base + r;
        if (node < NTOT) {
            float v[4];
#pragma unroll
            for (int j = 0; j < 4; j++) {
                v[j] = fmaxf(acc[i][j] + sBb[tx * 4 + j], 0.f);
                ssum[j] += v[j];
                sqr[j]   = fmaf(v[j], v[j], sqr[j]);
            }
            *(float4*)(hout + (size_t)node * 64 + tx * 4) = make_float4(v[0], v[1], v[2], v[3]);
            int g = sBatch[r];
            if (g != curg) {
                if (curg >= 0) {
#pragma unroll
                    for (int j = 0; j < 4; j++)
                        atomicAdd(&g_pooled[curg * 320 + layer * 64 + tx * 4 + j], run[j]);
                }
                curg = g;
#pragma unroll
                for (int j = 0; j < 4; j++) run[j] = v[j];
            } else {
#pragma unroll
                for (int j = 0; j < 4; j++) run[j] += v[j];
            }
        }
    }
    if (curg >= 0) {
#pragma unroll
        for (int j = 0; j < 4; j++)
            atomicAdd(&g_pooled[curg * 320 + layer * 64 + tx * 4 + j], run[j]);
    }

    // per-channel partial stats -> reuse sT (all GEMM2 reads complete after barrier)
    __syncthreads();
#pragma unroll
    for (int j = 0; j < 4; j++) {
        sT[ty * 64 + tx * 4 + j]        = ssum[j];
        sT[2048 + ty * 64 + tx * 4 + j] = sqr[j];
    }
    __syncthreads();
    if (t < 64) {
        float S = 0.f, Q = 0.f;
#pragma unroll
        for (int i2 = 0; i2 < 32; i2++) {
            S += sT[i2 * 64 + t];
            Q += sT[2048 + i2 * 64 + t];
        }
        g_stats[blockIdx.x * 128 + t]      = S;
        g_stats[blockIdx.x * 128 + 64 + t] = Q;
    }
}

// ---------------- BN stats finalize: mean/var -> scale/shift ----------------
__global__ void stats_kernel(const float* __restrict__ gamma_l,
                             const float* __restrict__ beta_l, int layer) {
    int c = blockIdx.x;   // 64 channels
    int t = threadIdx.x;  // 128
    __shared__ float sS[128], sQ[128];
    float S = 0.f, Q = 0.f;
    for (int b = t; b < NB; b += 128) {
        S += g_stats[b * 128 + c];
        Q += g_stats[b * 128 + 64 + c];
    }
    sS[t] = S; sQ[t] = Q;
    __syncthreads();
    for (int off = 64; off; off >>= 1) {
        if (t < off) { sS[t] += sS[t + off]; sQ[t] += sQ[t + off]; }
        __syncthreads();
    }
    if (t == 0) {
        float mean = sS[0] / (float)NTOT;
        float var  = sQ[0] / (float)NTOT - mean * mean;
        float rstd = rsqrtf(var + BN_EPS);
        float sc = rstd * gamma_l[c];
        g_scale[layer * 64 + c] = sc;
        g_shift[layer * 64 + c] = beta_l[c] - mean * sc;
    }
}

// ---------------- MLP head: BN fixup of pooled + fc1(ReLU) + fc2 ----------------
__global__ void mlp_kernel(const float* __restrict__ fc1W, const float* __restrict__ fc1b,
                           const float* __restrict__ fc2W, const float* __restrict__ fc2b,
                           float* __restrict__ out) {
    __shared__ float z[320];
    __shared__ float red[2];
    int g = blockIdx.x, t = threadIdx.x;  // 64 threads
    float cg = (float)g_cnt[g];
    for (int k = t; k < 320; k += 64)
        z[k] = fmaf(g_scale[k], g_pooled[g * 320 + k], cg * g_shift[k]);
    __syncthreads();
    float acc = fc1b[t];
    for (int k = 0; k < 320; k++)
        acc = fmaf(z[k], fc1W[k * 64 + t], acc);
    float h = fmaxf(acc, 0.f) * fc2W[t];
    for (int off = 16; off; off >>= 1) h += __shfl_down_sync(0xffffffffu, h, off);
    if ((t & 31) == 0) red[t >> 5] = h;
    __syncthreads();
    if (t == 0) out[g] = red[0] + red[1] + fc2b[0];
}

// ---------------- host launcher ----------------
extern "C" void kernel_launch(void* const* d_in, const int* in_sizes, int n_in,
                              void* d_out, int out_size) {
    const float* x     = (const float*)d_in[0];
    const int*   ei    = (const int*)d_in[1];
    const int*   batch = (const int*)d_in[2];
    const float* W1a   = (const float*)d_in[3];
    const float* b1a   = (const float*)d_in[4];
    const float* W1b   = (const float*)d_in[5];
    const float* b1b   = (const float*)d_in[6];
    const float* Wa    = (const float*)d_in[7];
    const float* ba    = (const float*)d_in[8];
    const float* Wb    = (const float*)d_in[9];
    const float* bb    = (const float*)d_in[10];
    const float* gamma = (const float*)d_in[11];
    const float* beta  = (const float*)d_in[12];
    const float* fc1W  = (const float*)d_in[13];
    const float* fc1b  = (const float*)d_in[14];
    const float* fc2W  = (const float*)d_in[15];
    const float* fc2b  = (const float*)d_in[16];
    float* out = (float*)d_out;

    const int* srcp = ei;
    const int* dstp = ei + ETOT;

    zero_kernel<<<256, 256>>>();
    hist_kernel<<<(ETOT + 255) / 256, 256>>>(dstp, batch);
    scanA_kernel<<<NSCAN, 1024>>>();
    scanB_kernel<<<1, 128>>>();
    scanC_kernel<<<NSCAN, 1024>>>();
    scatter_kernel<<<(ETOT + 255) / 256, 256>>>(srcp, dstp);
    gemm_in_kernel<<<NTOT / 4, 256>>>(x, W1a);

    // layer 0 (identity GEMM1; bias b1a folded into aggregation ReLU)
    gin_kernel<true><<<NB, 512>>>(nullptr, b1a, W1b, b1b, batch, 0);
    stats_kernel<<<64, 128>>>(gamma, beta, 0);

    for (int l = 1; l < 5; l++) {
        gin_kernel<false><<<NB, 512>>>(Wa + (l - 1) * 4096, ba + (l - 1) * 64,
                                       Wb + (l - 1) * 4096, bb + (l - 1) * 64,
                                       batch, l);
        stats_kernel<<<64, 128>>>(gamma + l * 64, beta + l * 64, l);
    }

    mlp_kernel<<<GTOT, 64>>>(fc1W, fc1b, fc2W, fc2b, out);
}

// round 4
// speedup vs baseline: 2.7551x; 2.7551x over previous
#include <cuda_runtime.h>
#include <cuda_bf16.h>
#include <cstdint>

// Problem constants (fixed shapes for this problem)
#define NTOT 100000
#define ETOT 1600000
#define GTOT 1024
#define NB   782          // ceil(NTOT/128) GIN blocks
#define NSCAN 98          // ceil(NTOT/1024)
#define BN_EPS 1e-5f
#define TSTR 68           // sT row stride in floats (272B = 17*16 -> float4-aligned)

// ---------------- device scratch (no runtime allocation allowed) ----------------
__device__ float g_bufA[NTOT * 64];       // ping
__device__ float g_bufB[NTOT * 64];       // pong
__device__ float g_agg[NTOT * 64];        // aggregation staging
__device__ int   g_deg[NTOT];
__device__ int   g_rowptr[NTOT + 1];
__device__ int   g_cursor[NTOT];
__device__ int   g_csr[ETOT];
__device__ int   g_bsum[NSCAN];
__device__ int   g_boff[NSCAN];
__device__ float g_stats[NB * 128];       // per-block [sum(64), sumsq(64)]
__device__ float g_scale[5 * 64];         // BN folded: scale = rstd*gamma
__device__ float g_shift[5 * 64];         // shift = beta - mean*scale
__device__ float g_pooled[GTOT * 320];    // raw (pre-BN) per-graph sums
__device__ int   g_cnt[GTOT];             // nodes per graph

// ---------------- packed fp32x2 helpers (Blackwell FFMA2) ----------------
__device__ __forceinline__ void fma2(unsigned long long& d, unsigned long long a,
                                     unsigned long long b) {
    asm("fma.rn.f32x2 %0, %1, %2, %0;" : "+l"(d) : "l"(a), "l"(b));
}
__device__ __forceinline__ unsigned long long dup2(float a) {
    unsigned long long r;
    asm("mov.b64 %0, {%1, %1};" : "=l"(r) : "f"(a));
    return r;
}
__device__ __forceinline__ float2 unpack2(unsigned long long v) {
    float2 r;
    asm("mov.b64 {%0, %1}, %2;" : "=f"(r.x), "=f"(r.y) : "l"(v));
    return r;
}

// ---------------- zero scratch ----------------
__global__ void zero_kernel() {
    int i0 = blockIdx.x * blockDim.x + threadIdx.x;
    int str = gridDim.x * blockDim.x;
    for (int i = i0; i < GTOT * 320; i += str) g_pooled[i] = 0.f;
    for (int i = i0; i < NTOT; i += str) g_deg[i] = 0;
    for (int i = i0; i < GTOT; i += str) g_cnt[i] = 0;
}

// ---------------- degree histogram + graph-size histogram ----------------
__global__ void hist_kernel(const int* __restrict__ dst, const int* __restrict__ batch) {
    int i = blockIdx.x * blockDim.x + threadIdx.x;
    if (i < ETOT) atomicAdd(&g_deg[dst[i]], 1);
    if (i < NTOT) atomicAdd(&g_cnt[batch[i]], 1);
}

// ---------------- 3-kernel coalesced exclusive scan of degrees ----------------
__global__ void scanA_kernel() {
    __shared__ int s[1024];
    int t = threadIdx.x;
    int i = blockIdx.x * 1024 + t;
    s[t] = (i < NTOT) ? g_deg[i] : 0;
    __syncthreads();
    for (int off = 512; off; off >>= 1) {
        if (t < off) s[t] += s[t + off];
        __syncthreads();
    }
    if (t == 0) g_bsum[blockIdx.x] = s[0];
}

__global__ void scanB_kernel() {
    int t = threadIdx.x;                       // 128 threads
    int v = (t < NSCAN) ? g_bsum[t] : 0;
    int x = v;
#pragma unroll
    for (int off = 1; off < 32; off <<= 1) {
        int y = __shfl_up_sync(0xffffffffu, x, off);
        if ((t & 31) >= off) x += y;
    }
    __shared__ int ws[4];
    if ((t & 31) == 31) ws[t >> 5] = x;
    __syncthreads();
    int add = 0;
#pragma unroll
    for (int w = 0; w < 4; w++) if (w < (t >> 5)) add += ws[w];
    int incl = x + add;
    if (t < NSCAN) g_boff[t] = incl - v;
    if (t == NSCAN - 1) g_rowptr[NTOT] = incl;
}

__global__ void scanC_kernel() {
    __shared__ int s[1024];
    int t = threadIdx.x;
    int i = blockIdx.x * 1024 + t;
    int v = (i < NTOT) ? g_deg[i] : 0;
    s[t] = v;
    __syncthreads();
    for (int off = 1; off < 1024; off <<= 1) {
        int tmp = (t >= off) ? s[t - off] : 0;
        __syncthreads();
        s[t] += tmp;
        __syncthreads();
    }
    int excl = s[t] - v + g_boff[blockIdx.x];
    if (i < NTOT) { g_rowptr[i] = excl; g_cursor[i] = excl; }
}

// ---------------- edge scatter into CSR ----------------
__global__ void scatter_kernel(const int* __restrict__ src, const int* __restrict__ dst) {
    int i = blockIdx.x * blockDim.x + threadIdx.x;
    if (i < ETOT) {
        int d = dst[i];
        int p = atomicAdd(&g_cursor[d], 1);
        g_csr[p] = src[i];
    }
}

// ---------------- q = x @ W1a (11 -> 64), no bias (bias folded into layer0) ----------------
__global__ void gemm_in_kernel(const float* __restrict__ x, const float* __restrict__ W1a) {
    __shared__ float sW[11 * 64];
    __shared__ float sx[4][12];
    int t = threadIdx.x;            // 256
    int nl = t >> 6, c = t & 63;
    int node = blockIdx.x * 4 + nl;
    for (int i = t; i < 11 * 64; i += 256) sW[i] = W1a[i];
    if (t < 44) {
        int n2 = t / 11, k = t % 11;
        int nn = blockIdx.x * 4 + n2;
        sx[n2][k] = (nn < NTOT) ? x[nn * 11 + k] : 0.f;
    }
    __syncthreads();
    if (node < NTOT) {
        float a = 0.f;
#pragma unroll
        for (int k = 0; k < 11; k++) a = fmaf(sx[nl][k], sW[k * 64 + c], a);
        g_bufA[node * 64 + c] = a;
    }
}

// ---------------- aggregation kernel (warp per node, shfl-broadcast CSR walk) ----------------
// Writes t = fold(h + sum_neighbors h) to g_agg.
//   FIRST:  t = ReLU(q + agg(q) + b1a)
//   else:   t = scale_prev*(h+agg(h)) + (deg+1)*shift_prev   (BN applied analytically)
template <bool FIRST>
__global__ void agg_kernel(const float* __restrict__ ba, int layer) {
    const float* hin = (layer & 1) ? g_bufB : g_bufA;
    int t = threadIdx.x, lane = t & 31;
    int gw = (blockIdx.x * blockDim.x + t) >> 5;
    int nwarps = (gridDim.x * blockDim.x) >> 5;

    float c0, c1, d0 = 0.f, d1 = 0.f;
    if (FIRST) {
        c0 = __ldg(&ba[2 * lane]); c1 = __ldg(&ba[2 * lane + 1]);
    } else {
        float2 sc = *(const float2*)(g_scale + (layer - 1) * 64 + 2 * lane);
        float2 sh = *(const float2*)(g_shift + (layer - 1) * 64 + 2 * lane);
        c0 = sc.x; c1 = sc.y; d0 = sh.x; d1 = sh.y;
    }

    for (int node = gw; node < NTOT; node += nwarps) {
        float2 own = *(const float2*)(hin + (size_t)node * 64 + 2 * lane);
        float ax = own.x, ay = own.y;
        int s0 = __ldg(&g_rowptr[node]), s1 = __ldg(&g_rowptr[node + 1]);
        for (int e = s0; e < s1; e += 32) {
            int m = s1 - e; if (m > 32) m = 32;
            int idx = (lane < m) ? __ldg(g_csr + e + lane) : 0;
#pragma unroll 4
            for (int ee = 0; ee < m; ++ee) {
                int s = __shfl_sync(0xffffffffu, idx, ee);
                float2 v = *(const float2*)(hin + (size_t)s * 64 + 2 * lane);
                ax += v.x; ay += v.y;
            }
        }
        if (FIRST) {
            ax = fmaxf(ax + c0, 0.f);
            ay = fmaxf(ay + c1, 0.f);
        } else {
            float kk = (float)(s1 - s0 + 1);
            ax = fmaf(c0, ax, kk * d0);
            ay = fmaf(c1, ay, kk * d1);
        }
        *(float2*)(g_agg + (size_t)node * 64 + 2 * lane) = make_float2(ax, ay);
    }
}

// ---------------- GEMM kernel: 2x (64x64) MLP + epilogue, FFMA2 inner loops ----------------
// 256 threads, 128 nodes per block. Weights in smem; tile in smem (stride TSTR=68).
template <bool FIRST>
__global__ void gemm_kernel(const float* __restrict__ Wa, const float* __restrict__ ba,
                            const float* __restrict__ Wb, const float* __restrict__ bb,
                            const int* __restrict__ batch, int layer) {
    float* hout = (layer & 1) ? g_bufA : g_bufB;

    __shared__ __align__(16) float sW1[64 * 64];
    __shared__ __align__(16) float sW2[64 * 64];
    __shared__ __align__(16) float sT[128 * TSTR];
    __shared__ float sBa[64];
    __shared__ float sBb[64];
    __shared__ int   sBatch[128];

    int t = threadIdx.x;                    // 256
    int base = blockIdx.x * 128;

    if (!FIRST) {
        for (int i = t; i < 4096; i += 256) sW1[i] = Wa[i];
    }
    for (int i = t; i < 4096; i += 256) sW2[i] = Wb[i];
    if (t < 64) {
        sBb[t] = bb[t];
        if (!FIRST) sBa[t] = ba[t];
    }
    if (t < 128) {
        int n = base + t;
        sBatch[t] = (n < NTOT) ? batch[n] : -1;
    }
    // load t tile from g_agg (coalesced float4; sT stride 68 keeps 16B alignment)
    for (int i = t; i < 2048; i += 256) {
        int row = i >> 4;
        int col = (i & 15) * 4;
        float4 v = make_float4(0.f, 0.f, 0.f, 0.f);
        if (base + row < NTOT) v = *(const float4*)(g_agg + (size_t)(base + row) * 64 + col);
        *(float4*)(sT + row * TSTR + col) = v;
    }
    __syncthreads();

    int ty = t >> 4, tx = t & 15;
    unsigned long long acc2[8][2];

    // ---- GEMM1 + ReLU ----
    if (!FIRST) {
#pragma unroll
        for (int i = 0; i < 8; i++) { acc2[i][0] = 0ull; acc2[i][1] = 0ull; }
#pragma unroll 8
        for (int k = 0; k < 64; k++) {
            ulonglong2 bw = *(const ulonglong2*)(sW1 + k * 64 + tx * 4);
#pragma unroll
            for (int i = 0; i < 8; i++) {
                unsigned long long aa = dup2(sT[(ty * 8 + i) * TSTR + k]);
                fma2(acc2[i][0], aa, bw.x);
                fma2(acc2[i][1], aa, bw.y);
            }
        }
        __syncthreads();
#pragma unroll
        for (int i = 0; i < 8; i++) {
            float2 p0 = unpack2(acc2[i][0]);
            float2 p1 = unpack2(acc2[i][1]);
            int r = ty * 8 + i;
            sT[r * TSTR + tx * 4 + 0] = fmaxf(p0.x + sBa[tx * 4 + 0], 0.f);
            sT[r * TSTR + tx * 4 + 1] = fmaxf(p0.y + sBa[tx * 4 + 1], 0.f);
            sT[r * TSTR + tx * 4 + 2] = fmaxf(p1.x + sBa[tx * 4 + 2], 0.f);
            sT[r * TSTR + tx * 4 + 3] = fmaxf(p1.y + sBa[tx * 4 + 3], 0.f);
        }
        __syncthreads();
    }

    // ---- GEMM2 ----
#pragma unroll
    for (int i = 0; i < 8; i++) { acc2[i][0] = 0ull; acc2[i][1] = 0ull; }
#pragma unroll 8
    for (int k = 0; k < 64; k++) {
        ulonglong2 bw = *(const ulonglong2*)(sW2 + k * 64 + tx * 4);
#pragma unroll
        for (int i = 0; i < 8; i++) {
            unsigned long long aa = dup2(sT[(ty * 8 + i) * TSTR + k]);
            fma2(acc2[i][0], aa, bw.x);
            fma2(acc2[i][1], aa, bw.y);
        }
    }

    // ---- epilogue: bias+ReLU, store h, stats partials, pooled run-length atomics ----
    float ssum[4] = {0.f, 0.f, 0.f, 0.f};
    float sqr[4]  = {0.f, 0.f, 0.f, 0.f};
    float run[4]  = {0.f, 0.f, 0.f, 0.f};
    int curg = -1;
#pragma unroll
    for (int i = 0; i < 8; i++) {
        int r = ty * 8 + i;
        int node = base + r;
        if (node < NTOT) {
            float2 p0 = unpack2(acc2[i][0]);
            float2 p1 = unpack2(acc2[i][1]);
            float v[4];
            v[0] = fmaxf(p0.x + sBb[tx * 4 + 0], 0.f);
            v[1] = fmaxf(p0.y + sBb[tx * 4 + 1], 0.f);
            v[2] = fmaxf(p1.x + sBb[tx * 4 + 2], 0.f);
            v[3] = fmaxf(p1.y + sBb[tx * 4 + 3], 0.f);
#pragma unroll
            for (int j = 0; j < 4; j++) {
                ssum[j] += v[j];
                sqr[j]   = fmaf(v[j], v[j], sqr[j]);
            }
            *(float4*)(hout + (size_t)node * 64 + tx * 4) = make_float4(v[0], v[1], v[2], v[3]);
            int g = sBatch[r];
            if (g != curg) {
                if (curg >= 0) {
#pragma unroll
                    for (int j = 0; j < 4; j++)
                        atomicAdd(&g_pooled[curg * 320 + layer * 64 + tx * 4 + j], run[j]);
                }
                curg = g;
#pragma unroll
                for (int j = 0; j < 4; j++) run[j] = v[j];
            } else {
#pragma unroll
                for (int j = 0; j < 4; j++) run[j] += v[j];
            }
        }
    }
    if (curg >= 0) {
#pragma unroll
        for (int j = 0; j < 4; j++)
            atomicAdd(&g_pooled[curg * 320 + layer * 64 + tx * 4 + j], run[j]);
    }

    // per-channel partial stats via sT reuse (all reads of sT done)
    __syncthreads();
#pragma unroll
    for (int j = 0; j < 4; j++) {
        sT[ty * 64 + tx * 4 + j]        = ssum[j];
        sT[1024 + ty * 64 + tx * 4 + j] = sqr[j];
    }
    __syncthreads();
    if (t < 64) {
        float S = 0.f, Q = 0.f;
#pragma unroll
        for (int i2 = 0; i2 < 16; i2++) {
            S += sT[i2 * 64 + t];
            Q += sT[1024 + i2 * 64 + t];
        }
        g_stats[blockIdx.x * 128 + t]      = S;
        g_stats[blockIdx.x * 128 + 64 + t] = Q;
    }
}

// ---------------- BN stats finalize: mean/var -> scale/shift ----------------
__global__ void stats_kernel(const float* __restrict__ gamma_l,
                             const float* __restrict__ beta_l, int layer) {
    int c = blockIdx.x;   // 64 channels
    int t = threadIdx.x;  // 128
    __shared__ float sS[128], sQ[128];
    float S = 0.f, Q = 0.f;
    for (int b = t; b < NB; b += 128) {
        S += g_stats[b * 128 + c];
        Q += g_stats[b * 128 + 64 + c];
    }
    sS[t] = S; sQ[t] = Q;
    __syncthreads();
    for (int off = 64; off; off >>= 1) {
        if (t < off) { sS[t] += sS[t + off]; sQ[t] += sQ[t + off]; }
        __syncthreads();
    }
    if (t == 0) {
        float mean = sS[0] / (float)NTOT;
        float var  = sQ[0] / (float)NTOT - mean * mean;
        float rstd = rsqrtf(var + BN_EPS);
        float sc = rstd * gamma_l[c];
        g_scale[layer * 64 + c] = sc;
        g_shift[layer * 64 + c] = beta_l[c] - mean * sc;
    }
}

// ---------------- MLP head: BN fixup of pooled + fc1(ReLU) + fc2 ----------------
__global__ void mlp_kernel(const float* __restrict__ fc1W, const float* __restrict__ fc1b,
                           const float* __restrict__ fc2W, const float* __restrict__ fc2b,
                           float* __restrict__ out) {
    __shared__ float z[320];
    __shared__ float red[2];
    int g = blockIdx.x, t = threadIdx.x;  // 64 threads
    float cg = (float)g_cnt[g];
    for (int k = t; k < 320; k += 64)
        z[k] = fmaf(g_scale[k], g_pooled[g * 320 + k], cg * g_shift[k]);
    __syncthreads();
    float acc = fc1b[t];
    for (int k = 0; k < 320; k++)
        acc = fmaf(z[k], fc1W[k * 64 + t], acc);
    float h = fmaxf(acc, 0.f) * fc2W[t];
    for (int off = 16; off; off >>= 1) h += __shfl_down_sync(0xffffffffu, h, off);
    if ((t & 31) == 0) red[t >> 5] = h;
    __syncthreads();
    if (t == 0) out[g] = red[0] + red[1] + fc2b[0];
}

// ---------------- host launcher ----------------
extern "C" void kernel_launch(void* const* d_in, const int* in_sizes, int n_in,
                              void* d_out, int out_size) {
    const float* x     = (const float*)d_in[0];
    const int*   ei    = (const int*)d_in[1];
    const int*   batch = (const int*)d_in[2];
    const float* W1a   = (const float*)d_in[3];
    const float* b1a   = (const float*)d_in[4];
    const float* W1b   = (const float*)d_in[5];
    const float* b1b   = (const float*)d_in[6];
    const float* Wa    = (const float*)d_in[7];
    const float* ba    = (const float*)d_in[8];
    const float* Wb    = (const float*)d_in[9];
    const float* bb    = (const float*)d_in[10];
    const float* gamma = (const float*)d_in[11];
    const float* beta  = (const float*)d_in[12];
    const float* fc1W  = (const float*)d_in[13];
    const float* fc1b  = (const float*)d_in[14];
    const float* fc2W  = (const float*)d_in[15];
    const float* fc2b  = (const float*)d_in[16];
    float* out = (float*)d_out;

    const int* srcp = ei;
    const int* dstp = ei + ETOT;

    zero_kernel<<<256, 256>>>();
    hist_kernel<<<(ETOT + 255) / 256, 256>>>(dstp, batch);
    scanA_kernel<<<NSCAN, 1024>>>();
    scanB_kernel<<<1, 128>>>();
    scanC_kernel<<<NSCAN, 1024>>>();
    scatter_kernel<<<(ETOT + 255) / 256, 256>>>(srcp, dstp);
    gemm_in_kernel<<<NTOT / 4, 256>>>(x, W1a);

    // layer 0 (identity GEMM1; bias b1a folded into aggregation ReLU)
    agg_kernel<true><<<1184, 256>>>(b1a, 0);
    gemm_kernel<true><<<NB, 256>>>(nullptr, nullptr, W1b, b1b, batch, 0);
    stats_kernel<<<64, 128>>>(gamma, beta, 0);

    for (int l = 1; l < 5; l++) {
        agg_kernel<false><<<1184, 256>>>(nullptr, l);
        gemm_kernel<false><<<NB, 256>>>(Wa + (l - 1) * 4096, ba + (l - 1) * 64,
                                        Wb + (l - 1) * 4096, bb + (l - 1) * 64,
                                        batch, l);
        stats_kernel<<<64, 128>>>(gamma + l * 64, beta + l * 64, l);
    }

    mlp_kernel<<<GTOT, 64>>>(fc1W, fc1b, fc2W, fc2b, out);
}